// round 14
// baseline (speedup 1.0000x reference)
#include <cuda_runtime.h>
#include <cuda_bf16.h>
#include <cuda_fp16.h>
#include <math.h>
#include <stdint.h>

// ===========================================================================
// AttentionLayer via mma.sync split GEMMs (fp32 accumulate in registers)
// B=64, T=1024, S=1024, C=E=512. Output = concat(out [B,T,C], attn [B,T,S])
//
// K1 (h = x@Win^T+b+te)  : 3-term bf16 split (scores amplify h errors)
// K2 (scores = h@esum)   : 3-term bf16 split
// K4 (ctx = attn@enc2)   : 1-pass fp16 (attn_f16 · enc2_f16)
// K5 (out = ctx@Wout^T+.): 1-pass fp16 (ctx_f16 · W_f16)
//
// R13 = R10 schedule (measured best) + software-pipelined fragment loads in
//       the GEMM inner loop (LDSM latency hiding on the single-warp path).
// ===========================================================================

static const float SQRT_HALF_F = 0.70710678118654752440f;

// ------------------------------ scratch ------------------------------------
__device__ __nv_bfloat16 g_xsplit  [(size_t)65536 * 1024];
__device__ __nv_bfloat16 g_hsplit  [(size_t)65536 * 1024];
__device__ __half        g_ctx_f16 [(size_t)65536 * 512];
__device__ __half        g_attn_f16[(size_t)65536 * 1024];
__device__ __nv_bfloat16 g_esumT   [(size_t)64 * 1024 * 1024];
__device__ __half        g_enc2T   [(size_t)64 * 512 * 1024];
__device__ __nv_bfloat16 g_winsplit [512 * 1024];
__device__ __half        g_wout_f16 [512 * 512];

// ------------------------------ helpers ------------------------------------
__device__ __forceinline__ uint32_t smem_u32(const void* p) {
    uint32_t a;
    asm("{ .reg .u64 t; cvta.to.shared.u64 t, %1; cvt.u32.u64 %0, t; }"
        : "=r"(a) : "l"(p));
    return a;
}

// pack two floats -> bf16x2 / f16x2 (first arg at lower address)
__device__ __forceinline__ uint32_t f2bf2(float lo, float hi) {
    uint32_t r;
    asm("cvt.rn.bf16x2.f32 %0, %1, %2;" : "=r"(r) : "f"(hi), "f"(lo));
    return r;
}
__device__ __forceinline__ uint32_t f2h2(float lo, float hi) {
    uint32_t r;
    asm("cvt.rn.f16x2.f32 %0, %1, %2;" : "=r"(r) : "f"(hi), "f"(lo));
    return r;
}
__device__ __forceinline__ float bfround(float v) {
    return __bfloat162float(__float2bfloat16(v));
}

__device__ __forceinline__ void cp16(uint32_t s, const void* g) {
    asm volatile("cp.async.cg.shared.global [%0], [%1], 16;" :: "r"(s), "l"(g));
}

__device__ __forceinline__ void ldsm4(uint32_t* r, uint32_t addr) {
    asm volatile("ldmatrix.sync.aligned.m8n8.x4.shared.b16 {%0,%1,%2,%3}, [%4];"
                 : "=r"(r[0]), "=r"(r[1]), "=r"(r[2]), "=r"(r[3]) : "r"(addr));
}

template <bool HALF>
__device__ __forceinline__ void mma16816(float* d, const uint32_t* a,
                                         uint32_t b0, uint32_t b1) {
    if (HALF)
        asm volatile(
            "mma.sync.aligned.m16n8k16.row.col.f32.f16.f16.f32 "
            "{%0,%1,%2,%3}, {%4,%5,%6,%7}, {%8,%9}, {%0,%1,%2,%3};"
            : "+f"(d[0]), "+f"(d[1]), "+f"(d[2]), "+f"(d[3])
            : "r"(a[0]), "r"(a[1]), "r"(a[2]), "r"(a[3]), "r"(b0), "r"(b1));
    else
        asm volatile(
            "mma.sync.aligned.m16n8k16.row.col.f32.bf16.bf16.f32 "
            "{%0,%1,%2,%3}, {%4,%5,%6,%7}, {%8,%9}, {%0,%1,%2,%3};"
            : "+f"(d[0]), "+f"(d[1]), "+f"(d[2]), "+f"(d[3])
            : "r"(a[0]), "r"(a[1]), "r"(a[2]), "r"(a[3]), "r"(b0), "r"(b1));
}

// ===========================================================================
// weight-norm + split [hi|lo] bf16: one block per row, cols=512
// ===========================================================================
__global__ void wn_split_kernel(const float* __restrict__ v, const float* __restrict__ g,
                                __nv_bfloat16* __restrict__ w, int cols)
{
    int r = blockIdx.x;
    int tid = threadIdx.x;
    const float* vr = v + (size_t)r * cols;

    float ss = 0.f;
    for (int c = tid; c < cols; c += blockDim.x) { float t = vr[c]; ss += t * t; }
    __shared__ float sm[32];
    #pragma unroll
    for (int o = 16; o > 0; o >>= 1) ss += __shfl_down_sync(0xffffffffu, ss, o);
    int warp = tid >> 5, lane = tid & 31;
    if (lane == 0) sm[warp] = ss;
    __syncthreads();
    int nw = blockDim.x >> 5;
    if (warp == 0) {
        float s2 = (lane < nw) ? sm[lane] : 0.f;
        #pragma unroll
        for (int o = 16; o > 0; o >>= 1) s2 += __shfl_down_sync(0xffffffffu, s2, o);
        if (lane == 0) sm[0] = s2;
    }
    __syncthreads();
    float scale = g[r] / sqrtf(sm[0]);
    __nv_bfloat16* wr = w + (size_t)r * (2 * cols);
    for (int c = tid; c < cols; c += blockDim.x) {
        float wv = vr[c] * scale;
        __nv_bfloat16 h = __float2bfloat16(wv);
        __nv_bfloat16 l = __float2bfloat16(wv - __bfloat162float(h));
        wr[c] = h;
        wr[cols + c] = l;
    }
}

// ===========================================================================
// weight-norm, single fp16 (for W_out): one block per row
// ===========================================================================
__global__ void wn_f16_kernel(const float* __restrict__ v, const float* __restrict__ g,
                              __half* __restrict__ w, int cols)
{
    int r = blockIdx.x;
    int tid = threadIdx.x;
    const float* vr = v + (size_t)r * cols;

    float ss = 0.f;
    for (int c = tid; c < cols; c += blockDim.x) { float t = vr[c]; ss += t * t; }
    __shared__ float sm[32];
    #pragma unroll
    for (int o = 16; o > 0; o >>= 1) ss += __shfl_down_sync(0xffffffffu, ss, o);
    int warp = tid >> 5, lane = tid & 31;
    if (lane == 0) sm[warp] = ss;
    __syncthreads();
    int nw = blockDim.x >> 5;
    if (warp == 0) {
        float s2 = (lane < nw) ? sm[lane] : 0.f;
        #pragma unroll
        for (int o = 16; o > 0; o >>= 1) s2 += __shfl_down_sync(0xffffffffu, s2, o);
        if (lane == 0) sm[0] = s2;
    }
    __syncthreads();
    float scale = g[r] / sqrtf(sm[0]);
    __half* wr = w + (size_t)r * cols;
    for (int c = tid; c < cols; c += blockDim.x)
        wr[c] = __float2half_rn(vr[c] * scale);
}

// ===========================================================================
// A-split [hi|lo] bf16:  x [rows,512] -> [rows,1024]
// ===========================================================================
__global__ void asplit_kernel(const float* __restrict__ in, __nv_bfloat16* __restrict__ out)
{
    size_t idx = (size_t)blockIdx.x * 256 + threadIdx.x;
    size_t row = idx >> 6;
    int g = (int)(idx & 63);
    const float* p = in + row * 512 + g * 8;
    float4 f0 = *(const float4*)p;
    float4 f1 = *(const float4*)(p + 4);
    float v[8] = {f0.x, f0.y, f0.z, f0.w, f1.x, f1.y, f1.z, f1.w};
    uint32_t hi[4], lo[4];
    #pragma unroll
    for (int q = 0; q < 4; q++) {
        hi[q] = f2bf2(v[2*q], v[2*q+1]);
        lo[q] = f2bf2(v[2*q] - bfround(v[2*q]), v[2*q+1] - bfround(v[2*q+1]));
    }
    __nv_bfloat16* o = out + row * 1024 + g * 8;
    *(uint4*)(o)       = *(uint4*)hi;
    *(uint4*)(o + 512) = *(uint4*)lo;
}

// ===========================================================================
// transpose + split [hi|lo] bf16: in0(+in1) [R, Cc] per batch -> out [Cc, 2R]
// ===========================================================================
__global__ void transpose_split_kernel(const float* __restrict__ in0,
                                       const float* __restrict__ in1,
                                       __nv_bfloat16* __restrict__ out,
                                       int R, int Cc, long long sIn, long long sOut)
{
    __shared__ float tile[64][33];
    int b = blockIdx.z;
    const float* A0 = in0 + (size_t)b * sIn;
    const float* A1 = in1 ? in1 + (size_t)b * sIn : nullptr;
    __nv_bfloat16* O = out + (size_t)b * sOut;
    int r0 = blockIdx.x * 64;
    int c0 = blockIdx.y * 32;
    int tid = threadIdx.x;

    #pragma unroll
    for (int i = 0; i < 8; i++) {
        int idx = i * 256 + tid;
        int rr = idx >> 5, cc = idx & 31;
        size_t off = (size_t)(r0 + rr) * Cc + c0 + cc;
        float vv = A0[off];
        if (A1) vv += A1[off];
        tile[rr][cc] = vv;
    }
    __syncthreads();

    int j = tid >> 3;
    int g = tid & 7;
    float v[8];
    #pragma unroll
    for (int u = 0; u < 8; u++) v[u] = tile[g * 8 + u][j];
    uint32_t hi[4], lo[4];
    #pragma unroll
    for (int p = 0; p < 4; p++) {
        hi[p] = f2bf2(v[2*p], v[2*p+1]);
        lo[p] = f2bf2(v[2*p] - bfround(v[2*p]), v[2*p+1] - bfround(v[2*p+1]));
    }
    __nv_bfloat16* ob = O + (size_t)(c0 + j) * (2 * R) + r0 + g * 8;
    *(uint4*)(ob)     = *(uint4*)hi;
    *(uint4*)(ob + R) = *(uint4*)lo;
}

// ===========================================================================
// transpose, single fp16: enc2 [R, Cc] per batch -> out [Cc, R]
// ===========================================================================
__global__ void transpose_f16_kernel(const float* __restrict__ in0,
                                     __half* __restrict__ out,
                                     int R, int Cc, long long sIn, long long sOut)
{
    __shared__ float tile[64][33];
    int b = blockIdx.z;
    const float* A0 = in0 + (size_t)b * sIn;
    __half* O = out + (size_t)b * sOut;
    int r0 = blockIdx.x * 64;
    int c0 = blockIdx.y * 32;
    int tid = threadIdx.x;

    #pragma unroll
    for (int i = 0; i < 8; i++) {
        int idx = i * 256 + tid;
        int rr = idx >> 5, cc = idx & 31;
        tile[rr][cc] = A0[(size_t)(r0 + rr) * Cc + c0 + cc];
    }
    __syncthreads();

    int j = tid >> 3;
    int g = tid & 7;
    float v[8];
    #pragma unroll
    for (int u = 0; u < 8; u++) v[u] = tile[g * 8 + u][j];
    uint32_t hv[4];
    #pragma unroll
    for (int p = 0; p < 4; p++) hv[p] = f2h2(v[2*p], v[2*p+1]);
    __half* ob = O + (size_t)(c0 + j) * R + r0 + g * 8;
    *(uint4*)(ob) = *(uint4*)hv;
}

// ===========================================================================
// mma.sync GEMM: C[128x128] = A x B^T over NSEC remapped K-sections.
// A row length AROW elems; B row length BROW. Section s uses +KLOG offset
// iff (AMAP>>s)&1 (resp BMAP). bf16 or fp16 operands per HALF.
// EPI: 0 = f32 C=acc*scale ; 1 = f32 C=(acc+bias+addend)*scale
//      3 = bf16 split [hi|lo] (acc+bias+addend)*scale ; 4 = fp16 single, *scale
// Inner loop software-pipelines fragment LDSMs (latency hiding).
// ===========================================================================
#define SMEM_BYTES 98304

template <int EPI, int KLOG, int NSEC, int AMAP, int BMAP, int AROW, int BROW, bool HALF>
__global__ __launch_bounds__(256, 2)
void mma_gemm(const uint16_t* __restrict__ A,
              const uint16_t* __restrict__ B,
              float* __restrict__ Cf, void* __restrict__ Cs,
              int N,
              long long sA, long long sB, long long sC,
              const float* __restrict__ bias,
              const float* __restrict__ addend,
              float scale)
{
    constexpr int SECLEN = KLOG / 64;      // chunks per section
    constexpr int NUMK   = NSEC * SECLEN;

    extern __shared__ __align__(1024) char smem[];
    uint32_t sbase = smem_u32(smem);
    const uint32_t st0 = sbase, st1 = sbase + 32768, st2 = sbase + 65536;

    int tid = threadIdx.x, wid = tid >> 5, lane = tid & 31;
    int z = blockIdx.z;
    A += (size_t)z * sA;
    B += (size_t)z * sB;
    int m0 = blockIdx.y * 128, n0 = blockIdx.x * 128;
    int warpM = (wid >> 1) * 32, warpN = (wid & 1) * 64;

    // ---- loader mapping: 4x16B cp.async per operand per chunk ----
    int c = tid & 7, rbase = tid >> 3;
    const size_t rsA = (size_t)32 * AROW * 2;   // 32 rows in bytes
    const size_t rsB = (size_t)32 * BROW * 2;
    const char* aRow = (const char*)(A + (size_t)(m0 + rbase) * AROW + c * 8);
    const char* bRow = (const char*)(B + (size_t)(n0 + rbase) * BROW + c * 8);
    uint32_t swo[4];
    #pragma unroll
    for (int i = 0; i < 4; i++) {
        uint32_t bo = (uint32_t)(rbase + 32 * i) * 128 + c * 16;
        swo[i] = bo ^ ((bo >> 3) & 0x70);
    }

    auto koffA = [](int ck) -> size_t {
        int sec = ck / SECLEN;
        int kk  = ck - sec * SECLEN;
        int map = (AMAP >> sec) & 1;
        return ((size_t)map * KLOG + (size_t)kk * 64) * 2;
    };
    auto koffB = [](int ck) -> size_t {
        int sec = ck / SECLEN;
        int kk  = ck - sec * SECLEN;
        int map = (BMAP >> sec) & 1;
        return ((size_t)map * KLOG + (size_t)kk * 64) * 2;
    };

#define LOADCHUNK(STG, CK) do {                                            \
        size_t oa_ = koffA(CK), ob_ = koffB(CK);                           \
        uint32_t ab_ = (STG), bb_ = (STG) + 16384;                         \
        cp16(ab_ + swo[0], aRow + oa_);                                    \
        cp16(ab_ + swo[1], aRow + oa_ + rsA);                              \
        cp16(ab_ + swo[2], aRow + oa_ + 2 * rsA);                          \
        cp16(ab_ + swo[3], aRow + oa_ + 3 * rsA);                          \
        cp16(bb_ + swo[0], bRow + ob_);                                    \
        cp16(bb_ + swo[1], bRow + ob_ + rsB);                              \
        cp16(bb_ + swo[2], bRow + ob_ + 2 * rsB);                          \
        cp16(bb_ + swo[3], bRow + ob_ + 3 * rsB);                          \
        asm volatile("cp.async.commit_group;" ::: "memory");               \
    } while (0)

    // ---- ldmatrix per-lane swizzled offsets ----
    uint32_t aoff[2], boff[4];
    {
        int l = lane;
        #pragma unroll
        for (int mt = 0; mt < 2; mt++) {
            int row = warpM + mt * 16 + (l & 15);
            uint32_t cb = (uint32_t)((l >> 4) << 4);
            aoff[mt] = (uint32_t)row * 128 + (cb ^ (((uint32_t)row & 7) << 4));
        }
        #pragma unroll
        for (int ng = 0; ng < 4; ng++) {
            int row = warpN + ng * 16 + (l & 7) + ((l >> 4) << 3);
            uint32_t cb = (uint32_t)(((l >> 3) & 1) << 4);
            boff[ng] = (uint32_t)row * 128 + (cb ^ (((uint32_t)row & 7) << 4));
        }
    }

    float d[2][8][4];
    #pragma unroll
    for (int mt = 0; mt < 2; mt++)
        #pragma unroll
        for (int nt = 0; nt < 8; nt++)
            #pragma unroll
            for (int q = 0; q < 4; q++) d[mt][nt][q] = 0.f;

    LOADCHUNK(st0, 0);
    LOADCHUNK(st1, 1);

    uint32_t stage[3] = { st0, st1, st2 };
    int cur = 0, nxt = 2;

    for (int ck = 0; ck < NUMK; ck++) {
        if (ck < NUMK - 1) asm volatile("cp.async.wait_group 1;" ::: "memory");
        else               asm volatile("cp.async.wait_group 0;" ::: "memory");
        __syncthreads();

        if (ck + 2 < NUMK) {
            LOADCHUNK(stage[nxt], ck + 2);
            nxt = (nxt == 2) ? 0 : nxt + 1;
        }

        uint32_t ab = stage[cur], bb = stage[cur] + 16384;
        cur = (cur == 2) ? 0 : cur + 1;
        #pragma unroll
        for (int ks = 0; ks < 4; ks++) {
            uint32_t kx = (uint32_t)ks << 5;
            // software-pipelined fragment loads: front-load a0,a1,b0,b1,b2
            uint32_t a[2][4], bq[4][4];
            ldsm4(a[0], ab + (aoff[0] ^ kx));
            ldsm4(a[1], ab + (aoff[1] ^ kx));
            ldsm4(bq[0], bb + (boff[0] ^ kx));
            ldsm4(bq[1], bb + (boff[1] ^ kx));
            ldsm4(bq[2], bb + (boff[2] ^ kx));
            // ng = 0 consumes bq[0] while bq[1],bq[2] are in flight
            mma16816<HALF>(d[0][0], a[0], bq[0][0], bq[0][1]);
            mma16816<HALF>(d[0][1], a[0], bq[0][2], bq[0][3]);
            mma16816<HALF>(d[1][0], a[1], bq[0][0], bq[0][1]);
            mma16816<HALF>(d[1][1], a[1], bq[0][2], bq[0][3]);
            ldsm4(bq[3], bb + (boff[3] ^ kx));
            // ng = 1..3
            #pragma unroll
            for (int ng = 1; ng < 4; ng++) {
                mma16816<HALF>(d[0][2 * ng],     a[0], bq[ng][0], bq[ng][1]);
                mma16816<HALF>(d[0][2 * ng + 1], a[0], bq[ng][2], bq[ng][3]);
                mma16816<HALF>(d[1][2 * ng],     a[1], bq[ng][0], bq[ng][1]);
                mma16816<HALF>(d[1][2 * ng + 1], a[1], bq[ng][2], bq[ng][3]);
            }
        }
    }
#undef LOADCHUNK

    // ---- epilogue ----
    int trow = lane >> 2, tcol = (lane & 3) * 2;
    #pragma unroll
    for (int mt = 0; mt < 2; mt++) {
        #pragma unroll
        for (int rr = 0; rr < 2; rr++) {
            size_t grow = (size_t)(m0 + warpM + mt * 16 + trow + rr * 8);
            #pragma unroll
            for (int nt = 0; nt < 8; nt++) {
                int gcol = n0 + warpN + nt * 8 + tcol;
                float v0 = d[mt][nt][rr * 2 + 0];
                float v1 = d[mt][nt][rr * 2 + 1];
                if (EPI == 1 || EPI == 3) {
                    float2 bq = *(const float2*)(bias + gcol);
                    float2 aq = *(const float2*)(addend + ((size_t)z * sC + grow * N) + gcol);
                    v0 = (v0 + bq.x + aq.x) * scale;
                    v1 = (v1 + bq.y + aq.y) * scale;
                } else {
                    v0 *= scale; v1 *= scale;
                }
                if (EPI <= 1) {
                    float* cp = Cf + (size_t)z * sC + grow * N + gcol;
                    *(float2*)cp = make_float2(v0, v1);
                } else if (EPI == 3) {
                    __nv_bfloat16* o = (__nv_bfloat16*)Cs +
                        (size_t)z * sC + grow * (size_t)(2 * N) + gcol;
                    uint32_t hi = f2bf2(v0, v1);
                    uint32_t lo = f2bf2(v0 - bfround(v0), v1 - bfround(v1));
                    *(uint32_t*)(o)     = hi;
                    *(uint32_t*)(o + N) = lo;
                } else {   // EPI == 4 : fp16 single
                    __half* o = (__half*)Cs + (size_t)z * sC + grow * (size_t)N + gcol;
                    *(uint32_t*)o = f2h2(v0, v1);
                }
            }
        }
    }
}

// ===========================================================================
// softmax over S=1024: writes f32 in place + single-fp16 copy for K4
// ===========================================================================
__global__ void softmax_f16_kernel(float* __restrict__ attn,
                                   __half* __restrict__ asp)
{
    size_t row = blockIdx.x;
    float* p = attn + row * 1024;
    int tid = threadIdx.x;

    float4 v = *(const float4*)&p[tid * 4];
    __shared__ float sm[8];

    float m = fmaxf(fmaxf(v.x, v.y), fmaxf(v.z, v.w));
    #pragma unroll
    for (int o = 16; o > 0; o >>= 1) m = fmaxf(m, __shfl_xor_sync(0xffffffffu, m, o));
    if ((tid & 31) == 0) sm[tid >> 5] = m;
    __syncthreads();
    float rmax = sm[0];
    #pragma unroll
    for (int w = 1; w < 8; w++) rmax = fmaxf(rmax, sm[w]);

    float e0 = expf(v.x - rmax), e1 = expf(v.y - rmax);
    float e2 = expf(v.z - rmax), e3 = expf(v.w - rmax);

    float s = (e0 + e1) + (e2 + e3);
    #pragma unroll
    for (int o = 16; o > 0; o >>= 1) s += __shfl_xor_sync(0xffffffffu, s, o);
    __syncthreads();
    if ((tid & 31) == 0) sm[tid >> 5] = s;
    __syncthreads();
    float rsum = 0.f;
    #pragma unroll
    for (int w = 0; w < 8; w++) rsum += sm[w];
    float inv = 1.f / rsum;

    float o0 = e0 * inv, o1 = e1 * inv, o2 = e2 * inv, o3 = e3 * inv;
    *(float4*)&p[tid * 4] = make_float4(o0, o1, o2, o3);

    uint32_t h01 = f2h2(o0, o1);
    uint32_t h23 = f2h2(o2, o3);
    *(uint2*)(asp + row * 1024 + tid * 4) = make_uint2(h01, h23);
}

// ===========================================================================
extern "C" void kernel_launch(void* const* d_in, const int* in_sizes, int n_in,
                              void* d_out, int out_size)
{
    const float* x     = (const float*)d_in[0];
    const float* te    = (const float*)d_in[1];
    const float* enc0  = (const float*)d_in[2];
    const float* enc1  = (const float*)d_in[3];
    const float* enc2  = (const float*)d_in[4];
    const float* in_v  = (const float*)d_in[5];
    const float* in_g  = (const float*)d_in[6];
    const float* in_b  = (const float*)d_in[7];
    const float* out_v = (const float*)d_in[8];
    const float* out_g = (const float*)d_in[9];
    const float* out_b = (const float*)d_in[10];

    float* out  = (float*)d_out;
    float* attn = out + (size_t)64 * 1024 * 512;

    __nv_bfloat16 *xsp, *hsp, *esumT, *winsp;
    __half *ctxh, *attnh, *enc2T, *wouth;
    cudaGetSymbolAddress((void**)&xsp,   g_xsplit);
    cudaGetSymbolAddress((void**)&hsp,   g_hsplit);
    cudaGetSymbolAddress((void**)&ctxh,  g_ctx_f16);
    cudaGetSymbolAddress((void**)&attnh, g_attn_f16);
    cudaGetSymbolAddress((void**)&esumT, g_esumT);
    cudaGetSymbolAddress((void**)&enc2T, g_enc2T);
    cudaGetSymbolAddress((void**)&winsp, g_winsplit);
    cudaGetSymbolAddress((void**)&wouth, g_wout_f16);

    // instantiations
    auto K1 = mma_gemm<3, 512, 3, 2, 4, 1024, 1024, false>;
    auto K2 = mma_gemm<0, 512, 3, 2, 4, 1024, 1024, false>;
    auto K4 = mma_gemm<4, 1024, 1, 0, 0, 1024, 1024, true>;   // single pass
    auto K5 = mma_gemm<1, 512, 1, 0, 0, 512, 512, true>;      // single pass
    cudaFuncSetAttribute(K1, cudaFuncAttributeMaxDynamicSharedMemorySize, SMEM_BYTES);
    cudaFuncSetAttribute(K2, cudaFuncAttributeMaxDynamicSharedMemorySize, SMEM_BYTES);
    cudaFuncSetAttribute(K4, cudaFuncAttributeMaxDynamicSharedMemorySize, SMEM_BYTES);
    cudaFuncSetAttribute(K5, cudaFuncAttributeMaxDynamicSharedMemorySize, SMEM_BYTES);

    // side stream + events for fork/join inside graph capture
    cudaStream_t s1;
    cudaStreamCreateWithFlags(&s1, cudaStreamNonBlocking);
    cudaEvent_t eFork, ePrep, eK1, eHalfB;
    cudaEventCreateWithFlags(&eFork,  cudaEventDisableTiming);
    cudaEventCreateWithFlags(&ePrep,  cudaEventDisableTiming);
    cudaEventCreateWithFlags(&eK1,    cudaEventDisableTiming);
    cudaEventCreateWithFlags(&eHalfB, cudaEventDisableTiming);

    // ---- fork ----
    cudaEventRecord(eFork, 0);
    cudaStreamWaitEvent(s1, eFork, 0);

    // side stream: operand prep for K2/K4/K5
    wn_f16_kernel<<<512, 256, 0, s1>>>(out_v, out_g, wouth, 512);
    transpose_split_kernel<<<dim3(8, 32, 64), 256, 0, s1>>>(
        enc0, enc1, esumT, 512, 1024, (long long)512 * 1024, (long long)1024 * 1024);
    transpose_f16_kernel<<<dim3(16, 16, 64), 256, 0, s1>>>(
        enc2, enc2T, 1024, 512, (long long)1024 * 512, (long long)512 * 1024);
    cudaEventRecord(ePrep, s1);

    // main stream: K1 chain
    wn_split_kernel<<<512, 256>>>(in_v, in_g, winsp, 512);
    asplit_kernel<<<16384, 256>>>(x, xsp);
    K1<<<dim3(4, 512, 1), 256, SMEM_BYTES>>>(
        (const uint16_t*)xsp, (const uint16_t*)winsp, nullptr, hsp,
        512, 0LL, 0LL, 0LL, in_b, te, SQRT_HALF_F);

    // join: main needs esumT before K2
    cudaStreamWaitEvent(0, ePrep, 0);
    cudaEventRecord(eK1, 0);
    cudaStreamWaitEvent(s1, eK1, 0);

    // ---- half-pipelined K2 -> softmax -> K4 (batches 0-31 / 32-63) ----
    const long long sA2 = (long long)1024 * 1024;   // hsp per-batch (elems)
    const long long sB2 = (long long)1024 * 1024;   // esumT per-batch
    const long long sC2 = (long long)1024 * 1024;   // attn per-batch
    const long long sA4 = (long long)1024 * 1024;   // attn_f16 per-batch
    const long long sB4 = (long long)512 * 1024;    // enc2T f16 per-batch
    const long long sC4 = (long long)1024 * 512;    // ctx_f16 per-batch

    // main: half A
    K2<<<dim3(8, 8, 32), 256, SMEM_BYTES>>>(
        (const uint16_t*)hsp, (const uint16_t*)esumT, attn, nullptr,
        1024, sA2, sB2, sC2, nullptr, nullptr, 1.0f);
    softmax_f16_kernel<<<32768, 256>>>(attn, attnh);
    K4<<<dim3(4, 8, 32), 256, SMEM_BYTES>>>(
        (const uint16_t*)attnh, (const uint16_t*)enc2T, nullptr, ctxh,
        512, sA4, sB4, sC4, nullptr, nullptr, 32.0f);

    // side: half B
    K2<<<dim3(8, 8, 32), 256, SMEM_BYTES, s1>>>(
        (const uint16_t*)(hsp + 32 * sA2), (const uint16_t*)(esumT + 32 * sB2),
        attn + 32 * sC2, nullptr, 1024, sA2, sB2, sC2, nullptr, nullptr, 1.0f);
    softmax_f16_kernel<<<32768, 256, 0, s1>>>(attn + 32 * sC2, attnh + 32 * sA4);
    K4<<<dim3(4, 8, 32), 256, SMEM_BYTES, s1>>>(
        (const uint16_t*)(attnh + 32 * sA4), (const uint16_t*)(enc2T + 32 * sB4),
        nullptr, ctxh + 32 * sC4, 512, sA4, sB4, sC4, nullptr, nullptr, 32.0f);
    cudaEventRecord(eHalfB, s1);

    // join before K5
    cudaStreamWaitEvent(0, eHalfB, 0);

    // K5: out = (ctx@Wout^T + b + x)*sqrt(.5)  f32, addend = x
    K5<<<dim3(4, 512, 1), 256, SMEM_BYTES>>>(
        (const uint16_t*)ctxh, (const uint16_t*)wouth, out, nullptr,
        512, 0LL, 0LL, 0LL, out_b, x, SQRT_HALF_F);
}

// round 15
// speedup vs baseline: 1.0246x; 1.0246x over previous
#include <cuda_runtime.h>
#include <cuda_bf16.h>
#include <cuda_fp16.h>
#include <math.h>
#include <stdint.h>

// ===========================================================================
// AttentionLayer via mma.sync split GEMMs (fp32 accumulate in registers)
// B=64, T=1024, S=1024, C=E=512. Output = concat(out [B,T,C], attn [B,T,S])
//
// K1 (h = x@Win^T+b+te)  : 3-term bf16 split (scores amplify h errors)
// K2 (scores = h@esum)   : 3-term bf16 split
// K4 (ctx = attn@enc2)   : 1-pass fp16 (attn_f16 · enc2_f16)
// K5 (out = ctx@Wout^T+.): 1-pass fp16 (ctx_f16 · W_f16)
//
// R15 = R10 (measured best) + warp-per-row softmax + prep micro-overlap.
// ===========================================================================

static const float SQRT_HALF_F = 0.70710678118654752440f;

// ------------------------------ scratch ------------------------------------
__device__ __nv_bfloat16 g_xsplit  [(size_t)65536 * 1024];
__device__ __nv_bfloat16 g_hsplit  [(size_t)65536 * 1024];
__device__ __half        g_ctx_f16 [(size_t)65536 * 512];
__device__ __half        g_attn_f16[(size_t)65536 * 1024];
__device__ __nv_bfloat16 g_esumT   [(size_t)64 * 1024 * 1024];
__device__ __half        g_enc2T   [(size_t)64 * 512 * 1024];
__device__ __nv_bfloat16 g_winsplit [512 * 1024];
__device__ __half        g_wout_f16 [512 * 512];

// ------------------------------ helpers ------------------------------------
__device__ __forceinline__ uint32_t smem_u32(const void* p) {
    uint32_t a;
    asm("{ .reg .u64 t; cvta.to.shared.u64 t, %1; cvt.u32.u64 %0, t; }"
        : "=r"(a) : "l"(p));
    return a;
}

// pack two floats -> bf16x2 / f16x2 (first arg at lower address)
__device__ __forceinline__ uint32_t f2bf2(float lo, float hi) {
    uint32_t r;
    asm("cvt.rn.bf16x2.f32 %0, %1, %2;" : "=r"(r) : "f"(hi), "f"(lo));
    return r;
}
__device__ __forceinline__ uint32_t f2h2(float lo, float hi) {
    uint32_t r;
    asm("cvt.rn.f16x2.f32 %0, %1, %2;" : "=r"(r) : "f"(hi), "f"(lo));
    return r;
}
__device__ __forceinline__ float bfround(float v) {
    return __bfloat162float(__float2bfloat16(v));
}

__device__ __forceinline__ void cp16(uint32_t s, const void* g) {
    asm volatile("cp.async.cg.shared.global [%0], [%1], 16;" :: "r"(s), "l"(g));
}

__device__ __forceinline__ void ldsm4(uint32_t* r, uint32_t addr) {
    asm volatile("ldmatrix.sync.aligned.m8n8.x4.shared.b16 {%0,%1,%2,%3}, [%4];"
                 : "=r"(r[0]), "=r"(r[1]), "=r"(r[2]), "=r"(r[3]) : "r"(addr));
}

template <bool HALF>
__device__ __forceinline__ void mma16816(float* d, const uint32_t* a,
                                         uint32_t b0, uint32_t b1) {
    if (HALF)
        asm volatile(
            "mma.sync.aligned.m16n8k16.row.col.f32.f16.f16.f32 "
            "{%0,%1,%2,%3}, {%4,%5,%6,%7}, {%8,%9}, {%0,%1,%2,%3};"
            : "+f"(d[0]), "+f"(d[1]), "+f"(d[2]), "+f"(d[3])
            : "r"(a[0]), "r"(a[1]), "r"(a[2]), "r"(a[3]), "r"(b0), "r"(b1));
    else
        asm volatile(
            "mma.sync.aligned.m16n8k16.row.col.f32.bf16.bf16.f32 "
            "{%0,%1,%2,%3}, {%4,%5,%6,%7}, {%8,%9}, {%0,%1,%2,%3};"
            : "+f"(d[0]), "+f"(d[1]), "+f"(d[2]), "+f"(d[3])
            : "r"(a[0]), "r"(a[1]), "r"(a[2]), "r"(a[3]), "r"(b0), "r"(b1));
}

// ===========================================================================
// weight-norm + split [hi|lo] bf16: one block per row, cols=512
// ===========================================================================
__global__ void wn_split_kernel(const float* __restrict__ v, const float* __restrict__ g,
                                __nv_bfloat16* __restrict__ w, int cols)
{
    int r = blockIdx.x;
    int tid = threadIdx.x;
    const float* vr = v + (size_t)r * cols;

    float ss = 0.f;
    for (int c = tid; c < cols; c += blockDim.x) { float t = vr[c]; ss += t * t; }
    __shared__ float sm[32];
    #pragma unroll
    for (int o = 16; o > 0; o >>= 1) ss += __shfl_down_sync(0xffffffffu, ss, o);
    int warp = tid >> 5, lane = tid & 31;
    if (lane == 0) sm[warp] = ss;
    __syncthreads();
    int nw = blockDim.x >> 5;
    if (warp == 0) {
        float s2 = (lane < nw) ? sm[lane] : 0.f;
        #pragma unroll
        for (int o = 16; o > 0; o >>= 1) s2 += __shfl_down_sync(0xffffffffu, s2, o);
        if (lane == 0) sm[0] = s2;
    }
    __syncthreads();
    float scale = g[r] / sqrtf(sm[0]);
    __nv_bfloat16* wr = w + (size_t)r * (2 * cols);
    for (int c = tid; c < cols; c += blockDim.x) {
        float wv = vr[c] * scale;
        __nv_bfloat16 h = __float2bfloat16(wv);
        __nv_bfloat16 l = __float2bfloat16(wv - __bfloat162float(h));
        wr[c] = h;
        wr[cols + c] = l;
    }
}

// ===========================================================================
// weight-norm, single fp16 (for W_out): one block per row
// ===========================================================================
__global__ void wn_f16_kernel(const float* __restrict__ v, const float* __restrict__ g,
                              __half* __restrict__ w, int cols)
{
    int r = blockIdx.x;
    int tid = threadIdx.x;
    const float* vr = v + (size_t)r * cols;

    float ss = 0.f;
    for (int c = tid; c < cols; c += blockDim.x) { float t = vr[c]; ss += t * t; }
    __shared__ float sm[32];
    #pragma unroll
    for (int o = 16; o > 0; o >>= 1) ss += __shfl_down_sync(0xffffffffu, ss, o);
    int warp = tid >> 5, lane = tid & 31;
    if (lane == 0) sm[warp] = ss;
    __syncthreads();
    int nw = blockDim.x >> 5;
    if (warp == 0) {
        float s2 = (lane < nw) ? sm[lane] : 0.f;
        #pragma unroll
        for (int o = 16; o > 0; o >>= 1) s2 += __shfl_down_sync(0xffffffffu, s2, o);
        if (lane == 0) sm[0] = s2;
    }
    __syncthreads();
    float scale = g[r] / sqrtf(sm[0]);
    __half* wr = w + (size_t)r * cols;
    for (int c = tid; c < cols; c += blockDim.x)
        wr[c] = __float2half_rn(vr[c] * scale);
}

// ===========================================================================
// A-split [hi|lo] bf16:  x [rows,512] -> [rows,1024]
// ===========================================================================
__global__ void asplit_kernel(const float* __restrict__ in, __nv_bfloat16* __restrict__ out)
{
    size_t idx = (size_t)blockIdx.x * 256 + threadIdx.x;
    size_t row = idx >> 6;
    int g = (int)(idx & 63);
    const float* p = in + row * 512 + g * 8;
    float4 f0 = *(const float4*)p;
    float4 f1 = *(const float4*)(p + 4);
    float v[8] = {f0.x, f0.y, f0.z, f0.w, f1.x, f1.y, f1.z, f1.w};
    uint32_t hi[4], lo[4];
    #pragma unroll
    for (int q = 0; q < 4; q++) {
        hi[q] = f2bf2(v[2*q], v[2*q+1]);
        lo[q] = f2bf2(v[2*q] - bfround(v[2*q]), v[2*q+1] - bfround(v[2*q+1]));
    }
    __nv_bfloat16* o = out + row * 1024 + g * 8;
    *(uint4*)(o)       = *(uint4*)hi;
    *(uint4*)(o + 512) = *(uint4*)lo;
}

// ===========================================================================
// transpose + split [hi|lo] bf16: in0(+in1) [R, Cc] per batch -> out [Cc, 2R]
// ===========================================================================
__global__ void transpose_split_kernel(const float* __restrict__ in0,
                                       const float* __restrict__ in1,
                                       __nv_bfloat16* __restrict__ out,
                                       int R, int Cc, long long sIn, long long sOut)
{
    __shared__ float tile[64][33];
    int b = blockIdx.z;
    const float* A0 = in0 + (size_t)b * sIn;
    const float* A1 = in1 ? in1 + (size_t)b * sIn : nullptr;
    __nv_bfloat16* O = out + (size_t)b * sOut;
    int r0 = blockIdx.x * 64;
    int c0 = blockIdx.y * 32;
    int tid = threadIdx.x;

    #pragma unroll
    for (int i = 0; i < 8; i++) {
        int idx = i * 256 + tid;
        int rr = idx >> 5, cc = idx & 31;
        size_t off = (size_t)(r0 + rr) * Cc + c0 + cc;
        float vv = A0[off];
        if (A1) vv += A1[off];
        tile[rr][cc] = vv;
    }
    __syncthreads();

    int j = tid >> 3;
    int g = tid & 7;
    float v[8];
    #pragma unroll
    for (int u = 0; u < 8; u++) v[u] = tile[g * 8 + u][j];
    uint32_t hi[4], lo[4];
    #pragma unroll
    for (int p = 0; p < 4; p++) {
        hi[p] = f2bf2(v[2*p], v[2*p+1]);
        lo[p] = f2bf2(v[2*p] - bfround(v[2*p]), v[2*p+1] - bfround(v[2*p+1]));
    }
    __nv_bfloat16* ob = O + (size_t)(c0 + j) * (2 * R) + r0 + g * 8;
    *(uint4*)(ob)     = *(uint4*)hi;
    *(uint4*)(ob + R) = *(uint4*)lo;
}

// ===========================================================================
// transpose, single fp16: enc2 [R, Cc] per batch -> out [Cc, R]
// ===========================================================================
__global__ void transpose_f16_kernel(const float* __restrict__ in0,
                                     __half* __restrict__ out,
                                     int R, int Cc, long long sIn, long long sOut)
{
    __shared__ float tile[64][33];
    int b = blockIdx.z;
    const float* A0 = in0 + (size_t)b * sIn;
    __half* O = out + (size_t)b * sOut;
    int r0 = blockIdx.x * 64;
    int c0 = blockIdx.y * 32;
    int tid = threadIdx.x;

    #pragma unroll
    for (int i = 0; i < 8; i++) {
        int idx = i * 256 + tid;
        int rr = idx >> 5, cc = idx & 31;
        tile[rr][cc] = A0[(size_t)(r0 + rr) * Cc + c0 + cc];
    }
    __syncthreads();

    int j = tid >> 3;
    int g = tid & 7;
    float v[8];
    #pragma unroll
    for (int u = 0; u < 8; u++) v[u] = tile[g * 8 + u][j];
    uint32_t hv[4];
    #pragma unroll
    for (int p = 0; p < 4; p++) hv[p] = f2h2(v[2*p], v[2*p+1]);
    __half* ob = O + (size_t)(c0 + j) * R + r0 + g * 8;
    *(uint4*)(ob) = *(uint4*)hv;
}

// ===========================================================================
// mma.sync GEMM: C[128x128] = A x B^T over NSEC remapped K-sections.
// A row length AROW elems; B row length BROW. Section s uses +KLOG offset
// iff (AMAP>>s)&1 (resp BMAP). bf16 or fp16 operands per HALF.
// EPI: 0 = f32 C=acc*scale ; 1 = f32 C=(acc+bias+addend)*scale
//      3 = bf16 split [hi|lo] (acc+bias+addend)*scale ; 4 = fp16 single, *scale
// ===========================================================================
#define SMEM_BYTES 98304

template <int EPI, int KLOG, int NSEC, int AMAP, int BMAP, int AROW, int BROW, bool HALF>
__global__ __launch_bounds__(256, 2)
void mma_gemm(const uint16_t* __restrict__ A,
              const uint16_t* __restrict__ B,
              float* __restrict__ Cf, void* __restrict__ Cs,
              int N,
              long long sA, long long sB, long long sC,
              const float* __restrict__ bias,
              const float* __restrict__ addend,
              float scale)
{
    constexpr int SECLEN = KLOG / 64;      // chunks per section
    constexpr int NUMK   = NSEC * SECLEN;

    extern __shared__ __align__(1024) char smem[];
    uint32_t sbase = smem_u32(smem);
    const uint32_t st0 = sbase, st1 = sbase + 32768, st2 = sbase + 65536;

    int tid = threadIdx.x, wid = tid >> 5, lane = tid & 31;
    int z = blockIdx.z;
    A += (size_t)z * sA;
    B += (size_t)z * sB;
    int m0 = blockIdx.y * 128, n0 = blockIdx.x * 128;
    int warpM = (wid >> 1) * 32, warpN = (wid & 1) * 64;

    // ---- loader mapping: 4x16B cp.async per operand per chunk ----
    int c = tid & 7, rbase = tid >> 3;
    const size_t rsA = (size_t)32 * AROW * 2;   // 32 rows in bytes
    const size_t rsB = (size_t)32 * BROW * 2;
    const char* aRow = (const char*)(A + (size_t)(m0 + rbase) * AROW + c * 8);
    const char* bRow = (const char*)(B + (size_t)(n0 + rbase) * BROW + c * 8);
    uint32_t swo[4];
    #pragma unroll
    for (int i = 0; i < 4; i++) {
        uint32_t bo = (uint32_t)(rbase + 32 * i) * 128 + c * 16;
        swo[i] = bo ^ ((bo >> 3) & 0x70);
    }

    auto koffA = [](int ck) -> size_t {
        int sec = ck / SECLEN;
        int kk  = ck - sec * SECLEN;
        int map = (AMAP >> sec) & 1;
        return ((size_t)map * KLOG + (size_t)kk * 64) * 2;
    };
    auto koffB = [](int ck) -> size_t {
        int sec = ck / SECLEN;
        int kk  = ck - sec * SECLEN;
        int map = (BMAP >> sec) & 1;
        return ((size_t)map * KLOG + (size_t)kk * 64) * 2;
    };

#define LOADCHUNK(STG, CK) do {                                            \
        size_t oa_ = koffA(CK), ob_ = koffB(CK);                           \
        uint32_t ab_ = (STG), bb_ = (STG) + 16384;                         \
        cp16(ab_ + swo[0], aRow + oa_);                                    \
        cp16(ab_ + swo[1], aRow + oa_ + rsA);                              \
        cp16(ab_ + swo[2], aRow + oa_ + 2 * rsA);                          \
        cp16(ab_ + swo[3], aRow + oa_ + 3 * rsA);                          \
        cp16(bb_ + swo[0], bRow + ob_);                                    \
        cp16(bb_ + swo[1], bRow + ob_ + rsB);                              \
        cp16(bb_ + swo[2], bRow + ob_ + 2 * rsB);                          \
        cp16(bb_ + swo[3], bRow + ob_ + 3 * rsB);                          \
        asm volatile("cp.async.commit_group;" ::: "memory");               \
    } while (0)

    // ---- ldmatrix per-lane swizzled offsets ----
    uint32_t aoff[2], boff[4];
    {
        int l = lane;
        #pragma unroll
        for (int mt = 0; mt < 2; mt++) {
            int row = warpM + mt * 16 + (l & 15);
            uint32_t cb = (uint32_t)((l >> 4) << 4);
            aoff[mt] = (uint32_t)row * 128 + (cb ^ (((uint32_t)row & 7) << 4));
        }
        #pragma unroll
        for (int ng = 0; ng < 4; ng++) {
            int row = warpN + ng * 16 + (l & 7) + ((l >> 4) << 3);
            uint32_t cb = (uint32_t)(((l >> 3) & 1) << 4);
            boff[ng] = (uint32_t)row * 128 + (cb ^ (((uint32_t)row & 7) << 4));
        }
    }

    float d[2][8][4];
    #pragma unroll
    for (int mt = 0; mt < 2; mt++)
        #pragma unroll
        for (int nt = 0; nt < 8; nt++)
            #pragma unroll
            for (int q = 0; q < 4; q++) d[mt][nt][q] = 0.f;

    LOADCHUNK(st0, 0);
    LOADCHUNK(st1, 1);

    uint32_t stage[3] = { st0, st1, st2 };
    int cur = 0, nxt = 2;

    for (int ck = 0; ck < NUMK; ck++) {
        if (ck < NUMK - 1) asm volatile("cp.async.wait_group 1;" ::: "memory");
        else               asm volatile("cp.async.wait_group 0;" ::: "memory");
        __syncthreads();

        if (ck + 2 < NUMK) {
            LOADCHUNK(stage[nxt], ck + 2);
            nxt = (nxt == 2) ? 0 : nxt + 1;
        }

        uint32_t ab = stage[cur], bb = stage[cur] + 16384;
        cur = (cur == 2) ? 0 : cur + 1;
        #pragma unroll
        for (int ks = 0; ks < 4; ks++) {
            uint32_t kx = (uint32_t)ks << 5;
            uint32_t a[2][4];
            ldsm4(a[0], ab + (aoff[0] ^ kx));
            ldsm4(a[1], ab + (aoff[1] ^ kx));
            #pragma unroll
            for (int ng = 0; ng < 4; ng++) {
                uint32_t bq[4];
                ldsm4(bq, bb + (boff[ng] ^ kx));
                #pragma unroll
                for (int mt = 0; mt < 2; mt++) {
                    mma16816<HALF>(d[mt][2 * ng],     a[mt], bq[0], bq[1]);
                    mma16816<HALF>(d[mt][2 * ng + 1], a[mt], bq[2], bq[3]);
                }
            }
        }
    }
#undef LOADCHUNK

    // ---- epilogue ----
    int trow = lane >> 2, tcol = (lane & 3) * 2;
    #pragma unroll
    for (int mt = 0; mt < 2; mt++) {
        #pragma unroll
        for (int rr = 0; rr < 2; rr++) {
            size_t grow = (size_t)(m0 + warpM + mt * 16 + trow + rr * 8);
            #pragma unroll
            for (int nt = 0; nt < 8; nt++) {
                int gcol = n0 + warpN + nt * 8 + tcol;
                float v0 = d[mt][nt][rr * 2 + 0];
                float v1 = d[mt][nt][rr * 2 + 1];
                if (EPI == 1 || EPI == 3) {
                    float2 bq = *(const float2*)(bias + gcol);
                    float2 aq = *(const float2*)(addend + ((size_t)z * sC + grow * N) + gcol);
                    v0 = (v0 + bq.x + aq.x) * scale;
                    v1 = (v1 + bq.y + aq.y) * scale;
                } else {
                    v0 *= scale; v1 *= scale;
                }
                if (EPI <= 1) {
                    float* cp = Cf + (size_t)z * sC + grow * N + gcol;
                    *(float2*)cp = make_float2(v0, v1);
                } else if (EPI == 3) {
                    __nv_bfloat16* o = (__nv_bfloat16*)Cs +
                        (size_t)z * sC + grow * (size_t)(2 * N) + gcol;
                    uint32_t hi = f2bf2(v0, v1);
                    uint32_t lo = f2bf2(v0 - bfround(v0), v1 - bfround(v1));
                    *(uint32_t*)(o)     = hi;
                    *(uint32_t*)(o + N) = lo;
                } else {   // EPI == 4 : fp16 single
                    __half* o = (__half*)Cs + (size_t)z * sC + grow * (size_t)N + gcol;
                    *(uint32_t*)o = f2h2(v0, v1);
                }
            }
        }
    }
}

// ===========================================================================
// softmax over S=1024, warp-per-row (8 rows per 256-thr block, no barriers):
// writes f32 in place + single-fp16 copy for K4
// ===========================================================================
__global__ void softmax_f16_kernel(float* __restrict__ attn,
                                   __half* __restrict__ asp)
{
    int lane = threadIdx.x & 31;
    size_t row = (size_t)blockIdx.x * 8 + (threadIdx.x >> 5);
    float* p = attn + row * 1024;

    // 8 float4 loads per lane: offsets lane*4 + c*128 (coalesced per chunk)
    float4 v[8];
    #pragma unroll
    for (int c2 = 0; c2 < 8; c2++)
        v[c2] = *(const float4*)&p[lane * 4 + c2 * 128];

    float m = -3.4e38f;
    #pragma unroll
    for (int c2 = 0; c2 < 8; c2++)
        m = fmaxf(m, fmaxf(fmaxf(v[c2].x, v[c2].y), fmaxf(v[c2].z, v[c2].w)));
    #pragma unroll
    for (int o = 16; o > 0; o >>= 1) m = fmaxf(m, __shfl_xor_sync(0xffffffffu, m, o));

    float s = 0.f;
    #pragma unroll
    for (int c2 = 0; c2 < 8; c2++) {
        v[c2].x = expf(v[c2].x - m);
        v[c2].y = expf(v[c2].y - m);
        v[c2].z = expf(v[c2].z - m);
        v[c2].w = expf(v[c2].w - m);
        s += (v[c2].x + v[c2].y) + (v[c2].z + v[c2].w);
    }
    #pragma unroll
    for (int o = 16; o > 0; o >>= 1) s += __shfl_xor_sync(0xffffffffu, s, o);
    float inv = 1.f / s;

    __half* ah = asp + row * 1024;
    #pragma unroll
    for (int c2 = 0; c2 < 8; c2++) {
        float o0 = v[c2].x * inv, o1 = v[c2].y * inv;
        float o2 = v[c2].z * inv, o3 = v[c2].w * inv;
        *(float4*)&p[lane * 4 + c2 * 128] = make_float4(o0, o1, o2, o3);
        *(uint2*)&ah[lane * 4 + c2 * 128] = make_uint2(f2h2(o0, o1), f2h2(o2, o3));
    }
}

// ===========================================================================
extern "C" void kernel_launch(void* const* d_in, const int* in_sizes, int n_in,
                              void* d_out, int out_size)
{
    const float* x     = (const float*)d_in[0];
    const float* te    = (const float*)d_in[1];
    const float* enc0  = (const float*)d_in[2];
    const float* enc1  = (const float*)d_in[3];
    const float* enc2  = (const float*)d_in[4];
    const float* in_v  = (const float*)d_in[5];
    const float* in_g  = (const float*)d_in[6];
    const float* in_b  = (const float*)d_in[7];
    const float* out_v = (const float*)d_in[8];
    const float* out_g = (const float*)d_in[9];
    const float* out_b = (const float*)d_in[10];

    float* out  = (float*)d_out;
    float* attn = out + (size_t)64 * 1024 * 512;

    __nv_bfloat16 *xsp, *hsp, *esumT, *winsp;
    __half *ctxh, *attnh, *enc2T, *wouth;
    cudaGetSymbolAddress((void**)&xsp,   g_xsplit);
    cudaGetSymbolAddress((void**)&hsp,   g_hsplit);
    cudaGetSymbolAddress((void**)&ctxh,  g_ctx_f16);
    cudaGetSymbolAddress((void**)&attnh, g_attn_f16);
    cudaGetSymbolAddress((void**)&esumT, g_esumT);
    cudaGetSymbolAddress((void**)&enc2T, g_enc2T);
    cudaGetSymbolAddress((void**)&winsp, g_winsplit);
    cudaGetSymbolAddress((void**)&wouth, g_wout_f16);

    // instantiations
    auto K1 = mma_gemm<3, 512, 3, 2, 4, 1024, 1024, false>;
    auto K2 = mma_gemm<0, 512, 3, 2, 4, 1024, 1024, false>;
    auto K4 = mma_gemm<4, 1024, 1, 0, 0, 1024, 1024, true>;   // single pass
    auto K5 = mma_gemm<1, 512, 1, 0, 0, 512, 512, true>;      // single pass
    cudaFuncSetAttribute(K1, cudaFuncAttributeMaxDynamicSharedMemorySize, SMEM_BYTES);
    cudaFuncSetAttribute(K2, cudaFuncAttributeMaxDynamicSharedMemorySize, SMEM_BYTES);
    cudaFuncSetAttribute(K4, cudaFuncAttributeMaxDynamicSharedMemorySize, SMEM_BYTES);
    cudaFuncSetAttribute(K5, cudaFuncAttributeMaxDynamicSharedMemorySize, SMEM_BYTES);

    // side stream + events for fork/join inside graph capture
    cudaStream_t s1;
    cudaStreamCreateWithFlags(&s1, cudaStreamNonBlocking);
    cudaEvent_t eFork, eWn, ePrep, eK1, eHalfB;
    cudaEventCreateWithFlags(&eFork,  cudaEventDisableTiming);
    cudaEventCreateWithFlags(&eWn,    cudaEventDisableTiming);
    cudaEventCreateWithFlags(&ePrep,  cudaEventDisableTiming);
    cudaEventCreateWithFlags(&eK1,    cudaEventDisableTiming);
    cudaEventCreateWithFlags(&eHalfB, cudaEventDisableTiming);

    // ---- fork ----
    cudaEventRecord(eFork, 0);
    cudaStreamWaitEvent(s1, eFork, 0);

    // side stream: K1's weights first (so main's asplit overlaps), then preps
    wn_split_kernel<<<512, 256, 0, s1>>>(in_v, in_g, winsp, 512);
    cudaEventRecord(eWn, s1);
    wn_f16_kernel<<<512, 256, 0, s1>>>(out_v, out_g, wouth, 512);
    transpose_split_kernel<<<dim3(8, 32, 64), 256, 0, s1>>>(
        enc0, enc1, esumT, 512, 1024, (long long)512 * 1024, (long long)1024 * 1024);
    transpose_f16_kernel<<<dim3(16, 16, 64), 256, 0, s1>>>(
        enc2, enc2T, 1024, 512, (long long)1024 * 512, (long long)512 * 1024);
    cudaEventRecord(ePrep, s1);

    // main stream: input split (overlaps wn_split), then K1
    asplit_kernel<<<16384, 256>>>(x, xsp);
    cudaStreamWaitEvent(0, eWn, 0);
    K1<<<dim3(4, 512, 1), 256, SMEM_BYTES>>>(
        (const uint16_t*)xsp, (const uint16_t*)winsp, nullptr, hsp,
        512, 0LL, 0LL, 0LL, in_b, te, SQRT_HALF_F);

    // join: main needs esumT before K2
    cudaStreamWaitEvent(0, ePrep, 0);
    cudaEventRecord(eK1, 0);
    cudaStreamWaitEvent(s1, eK1, 0);

    // ---- half-pipelined K2 -> softmax -> K4 (batches 0-31 / 32-63) ----
    const long long sA2 = (long long)1024 * 1024;   // hsp per-batch (elems)
    const long long sB2 = (long long)1024 * 1024;   // esumT per-batch
    const long long sC2 = (long long)1024 * 1024;   // attn per-batch
    const long long sA4 = (long long)1024 * 1024;   // attn_f16 per-batch
    const long long sB4 = (long long)512 * 1024;    // enc2T f16 per-batch
    const long long sC4 = (long long)1024 * 512;    // ctx_f16 per-batch

    // main: half A
    K2<<<dim3(8, 8, 32), 256, SMEM_BYTES>>>(
        (const uint16_t*)hsp, (const uint16_t*)esumT, attn, nullptr,
        1024, sA2, sB2, sC2, nullptr, nullptr, 1.0f);
    softmax_f16_kernel<<<4096, 256>>>(attn, attnh);
    K4<<<dim3(4, 8, 32), 256, SMEM_BYTES>>>(
        (const uint16_t*)attnh, (const uint16_t*)enc2T, nullptr, ctxh,
        512, sA4, sB4, sC4, nullptr, nullptr, 32.0f);

    // side: half B
    K2<<<dim3(8, 8, 32), 256, SMEM_BYTES, s1>>>(
        (const uint16_t*)(hsp + 32 * sA2), (const uint16_t*)(esumT + 32 * sB2),
        attn + 32 * sC2, nullptr, 1024, sA2, sB2, sC2, nullptr, nullptr, 1.0f);
    softmax_f16_kernel<<<4096, 256, 0, s1>>>(attn + 32 * sC2, attnh + 32 * sA4);
    K4<<<dim3(4, 8, 32), 256, SMEM_BYTES, s1>>>(
        (const uint16_t*)(attnh + 32 * sA4), (const uint16_t*)(enc2T + 32 * sB4),
        nullptr, ctxh + 32 * sC4, 512, sA4, sB4, sC4, nullptr, nullptr, 32.0f);
    cudaEventRecord(eHalfB, s1);

    // join before K5
    cudaStreamWaitEvent(0, eHalfB, 0);

    // K5: out = (ctx@Wout^T + b + x)*sqrt(.5)  f32, addend = x
    K5<<<dim3(4, 512, 1), 256, SMEM_BYTES>>>(
        (const uint16_t*)ctxh, (const uint16_t*)wouth, out, nullptr,
        512, 0LL, 0LL, 0LL, out_b, x, SQRT_HALF_F);
}

// round 16
// speedup vs baseline: 1.0451x; 1.0200x over previous
#include <cuda_runtime.h>
#include <cuda_bf16.h>
#include <cuda_fp16.h>
#include <math.h>
#include <stdint.h>

// ===========================================================================
// AttentionLayer via mma.sync split GEMMs (fp32 accumulate in registers)
// B=64, T=1024, S=1024, C=E=512. Output = concat(out [B,T,C], attn [B,T,S])
//
// K1 (h = x@Win^T+b+te)  : 3-term bf16 split (scores amplify h errors)
// K2 (scores = h@esum)   : 3-term bf16 split
// KE (E2W = 32*W@enc2^T) : 1-pass fp16, precomputed on side stream
// K6 (out = attn@E2W+b+x): 1-pass fp16  [replaces K4->K5 chain]
// ===========================================================================

static const float SQRT_HALF_F = 0.70710678118654752440f;

// ------------------------------ scratch ------------------------------------
__device__ __nv_bfloat16 g_xsplit  [(size_t)65536 * 1024];
__device__ __nv_bfloat16 g_hsplit  [(size_t)65536 * 1024];
__device__ __half        g_attn_f16[(size_t)65536 * 1024];
__device__ __nv_bfloat16 g_esumT   [(size_t)64 * 1024 * 1024];
__device__ __half        g_enc2h   [(size_t)64 * 1024 * 512];
__device__ __half        g_e2w     [(size_t)64 * 512 * 1024];
__device__ __nv_bfloat16 g_winsplit [512 * 1024];
__device__ __half        g_wout_f16 [512 * 512];

// ------------------------------ helpers ------------------------------------
__device__ __forceinline__ uint32_t smem_u32(const void* p) {
    uint32_t a;
    asm("{ .reg .u64 t; cvta.to.shared.u64 t, %1; cvt.u32.u64 %0, t; }"
        : "=r"(a) : "l"(p));
    return a;
}

// pack two floats -> bf16x2 / f16x2 (first arg at lower address)
__device__ __forceinline__ uint32_t f2bf2(float lo, float hi) {
    uint32_t r;
    asm("cvt.rn.bf16x2.f32 %0, %1, %2;" : "=r"(r) : "f"(hi), "f"(lo));
    return r;
}
__device__ __forceinline__ uint32_t f2h2(float lo, float hi) {
    uint32_t r;
    asm("cvt.rn.f16x2.f32 %0, %1, %2;" : "=r"(r) : "f"(hi), "f"(lo));
    return r;
}
__device__ __forceinline__ float bfround(float v) {
    return __bfloat162float(__float2bfloat16(v));
}

__device__ __forceinline__ void cp16(uint32_t s, const void* g) {
    asm volatile("cp.async.cg.shared.global [%0], [%1], 16;" :: "r"(s), "l"(g));
}

__device__ __forceinline__ void ldsm4(uint32_t* r, uint32_t addr) {
    asm volatile("ldmatrix.sync.aligned.m8n8.x4.shared.b16 {%0,%1,%2,%3}, [%4];"
                 : "=r"(r[0]), "=r"(r[1]), "=r"(r[2]), "=r"(r[3]) : "r"(addr));
}

template <bool HALF>
__device__ __forceinline__ void mma16816(float* d, const uint32_t* a,
                                         uint32_t b0, uint32_t b1) {
    if (HALF)
        asm volatile(
            "mma.sync.aligned.m16n8k16.row.col.f32.f16.f16.f32 "
            "{%0,%1,%2,%3}, {%4,%5,%6,%7}, {%8,%9}, {%0,%1,%2,%3};"
            : "+f"(d[0]), "+f"(d[1]), "+f"(d[2]), "+f"(d[3])
            : "r"(a[0]), "r"(a[1]), "r"(a[2]), "r"(a[3]), "r"(b0), "r"(b1));
    else
        asm volatile(
            "mma.sync.aligned.m16n8k16.row.col.f32.bf16.bf16.f32 "
            "{%0,%1,%2,%3}, {%4,%5,%6,%7}, {%8,%9}, {%0,%1,%2,%3};"
            : "+f"(d[0]), "+f"(d[1]), "+f"(d[2]), "+f"(d[3])
            : "r"(a[0]), "r"(a[1]), "r"(a[2]), "r"(a[3]), "r"(b0), "r"(b1));
}

// ===========================================================================
// weight-norm + split [hi|lo] bf16: one block per row, cols=512
// ===========================================================================
__global__ void wn_split_kernel(const float* __restrict__ v, const float* __restrict__ g,
                                __nv_bfloat16* __restrict__ w, int cols)
{
    int r = blockIdx.x;
    int tid = threadIdx.x;
    const float* vr = v + (size_t)r * cols;

    float ss = 0.f;
    for (int c = tid; c < cols; c += blockDim.x) { float t = vr[c]; ss += t * t; }
    __shared__ float sm[32];
    #pragma unroll
    for (int o = 16; o > 0; o >>= 1) ss += __shfl_down_sync(0xffffffffu, ss, o);
    int warp = tid >> 5, lane = tid & 31;
    if (lane == 0) sm[warp] = ss;
    __syncthreads();
    int nw = blockDim.x >> 5;
    if (warp == 0) {
        float s2 = (lane < nw) ? sm[lane] : 0.f;
        #pragma unroll
        for (int o = 16; o > 0; o >>= 1) s2 += __shfl_down_sync(0xffffffffu, s2, o);
        if (lane == 0) sm[0] = s2;
    }
    __syncthreads();
    float scale = g[r] / sqrtf(sm[0]);
    __nv_bfloat16* wr = w + (size_t)r * (2 * cols);
    for (int c = tid; c < cols; c += blockDim.x) {
        float wv = vr[c] * scale;
        __nv_bfloat16 h = __float2bfloat16(wv);
        __nv_bfloat16 l = __float2bfloat16(wv - __bfloat162float(h));
        wr[c] = h;
        wr[cols + c] = l;
    }
}

// ===========================================================================
// weight-norm, single fp16 (for W_out): one block per row
// ===========================================================================
__global__ void wn_f16_kernel(const float* __restrict__ v, const float* __restrict__ g,
                              __half* __restrict__ w, int cols)
{
    int r = blockIdx.x;
    int tid = threadIdx.x;
    const float* vr = v + (size_t)r * cols;

    float ss = 0.f;
    for (int c = tid; c < cols; c += blockDim.x) { float t = vr[c]; ss += t * t; }
    __shared__ float sm[32];
    #pragma unroll
    for (int o = 16; o > 0; o >>= 1) ss += __shfl_down_sync(0xffffffffu, ss, o);
    int warp = tid >> 5, lane = tid & 31;
    if (lane == 0) sm[warp] = ss;
    __syncthreads();
    int nw = blockDim.x >> 5;
    if (warp == 0) {
        float s2 = (lane < nw) ? sm[lane] : 0.f;
        #pragma unroll
        for (int o = 16; o > 0; o >>= 1) s2 += __shfl_down_sync(0xffffffffu, s2, o);
        if (lane == 0) sm[0] = s2;
    }
    __syncthreads();
    float scale = g[r] / sqrtf(sm[0]);
    __half* wr = w + (size_t)r * cols;
    for (int c = tid; c < cols; c += blockDim.x)
        wr[c] = __float2half_rn(vr[c] * scale);
}

// ===========================================================================
// A-split [hi|lo] bf16:  x [rows,512] -> [rows,1024]
// ===========================================================================
__global__ void asplit_kernel(const float* __restrict__ in, __nv_bfloat16* __restrict__ out)
{
    size_t idx = (size_t)blockIdx.x * 256 + threadIdx.x;
    size_t row = idx >> 6;
    int g = (int)(idx & 63);
    const float* p = in + row * 512 + g * 8;
    float4 f0 = *(const float4*)p;
    float4 f1 = *(const float4*)(p + 4);
    float v[8] = {f0.x, f0.y, f0.z, f0.w, f1.x, f1.y, f1.z, f1.w};
    uint32_t hi[4], lo[4];
    #pragma unroll
    for (int q = 0; q < 4; q++) {
        hi[q] = f2bf2(v[2*q], v[2*q+1]);
        lo[q] = f2bf2(v[2*q] - bfround(v[2*q]), v[2*q+1] - bfround(v[2*q+1]));
    }
    __nv_bfloat16* o = out + row * 1024 + g * 8;
    *(uint4*)(o)       = *(uint4*)hi;
    *(uint4*)(o + 512) = *(uint4*)lo;
}

// ===========================================================================
// transpose + split [hi|lo] bf16: in0(+in1) [R, Cc] per batch -> out [Cc, 2R]
// ===========================================================================
__global__ void transpose_split_kernel(const float* __restrict__ in0,
                                       const float* __restrict__ in1,
                                       __nv_bfloat16* __restrict__ out,
                                       int R, int Cc, long long sIn, long long sOut)
{
    __shared__ float tile[64][33];
    int b = blockIdx.z;
    const float* A0 = in0 + (size_t)b * sIn;
    const float* A1 = in1 ? in1 + (size_t)b * sIn : nullptr;
    __nv_bfloat16* O = out + (size_t)b * sOut;
    int r0 = blockIdx.x * 64;
    int c0 = blockIdx.y * 32;
    int tid = threadIdx.x;

    #pragma unroll
    for (int i = 0; i < 8; i++) {
        int idx = i * 256 + tid;
        int rr = idx >> 5, cc = idx & 31;
        size_t off = (size_t)(r0 + rr) * Cc + c0 + cc;
        float vv = A0[off];
        if (A1) vv += A1[off];
        tile[rr][cc] = vv;
    }
    __syncthreads();

    int j = tid >> 3;
    int g = tid & 7;
    float v[8];
    #pragma unroll
    for (int u = 0; u < 8; u++) v[u] = tile[g * 8 + u][j];
    uint32_t hi[4], lo[4];
    #pragma unroll
    for (int p = 0; p < 4; p++) {
        hi[p] = f2bf2(v[2*p], v[2*p+1]);
        lo[p] = f2bf2(v[2*p] - bfround(v[2*p]), v[2*p+1] - bfround(v[2*p+1]));
    }
    __nv_bfloat16* ob = O + (size_t)(c0 + j) * (2 * R) + r0 + g * 8;
    *(uint4*)(ob)     = *(uint4*)hi;
    *(uint4*)(ob + R) = *(uint4*)lo;
}

// ===========================================================================
// elementwise f32 -> f16 convert (8 elems per thread)
// ===========================================================================
__global__ void f16cvt_kernel(const float* __restrict__ in, __half* __restrict__ out)
{
    size_t i = ((size_t)blockIdx.x * 256 + threadIdx.x) * 8;
    float4 a = *(const float4*)(in + i);
    float4 b = *(const float4*)(in + i + 4);
    uint4 r;
    r.x = f2h2(a.x, a.y);
    r.y = f2h2(a.z, a.w);
    r.z = f2h2(b.x, b.y);
    r.w = f2h2(b.z, b.w);
    *(uint4*)(out + i) = r;
}

// ===========================================================================
// mma.sync GEMM: C[128x128] = A x B^T over NSEC remapped K-sections.
// A row length AROW elems; B row length BROW. Section s uses +KLOG offset
// iff (AMAP>>s)&1 (resp BMAP). bf16 or fp16 operands per HALF.
// EPI: 0 = f32 C=acc*scale ; 1 = f32 C=(acc+bias+addend)*scale
//      3 = bf16 split [hi|lo] (acc+bias+addend)*scale ; 4 = fp16 single, *scale
// ===========================================================================
#define SMEM_BYTES 98304

template <int EPI, int KLOG, int NSEC, int AMAP, int BMAP, int AROW, int BROW, bool HALF>
__global__ __launch_bounds__(256, 2)
void mma_gemm(const uint16_t* __restrict__ A,
              const uint16_t* __restrict__ B,
              float* __restrict__ Cf, void* __restrict__ Cs,
              int N,
              long long sA, long long sB, long long sC,
              const float* __restrict__ bias,
              const float* __restrict__ addend,
              float scale)
{
    constexpr int SECLEN = KLOG / 64;      // chunks per section
    constexpr int NUMK   = NSEC * SECLEN;

    extern __shared__ __align__(1024) char smem[];
    uint32_t sbase = smem_u32(smem);
    const uint32_t st0 = sbase, st1 = sbase + 32768, st2 = sbase + 65536;

    int tid = threadIdx.x, wid = tid >> 5, lane = tid & 31;
    int z = blockIdx.z;
    A += (size_t)z * sA;
    B += (size_t)z * sB;
    int m0 = blockIdx.y * 128, n0 = blockIdx.x * 128;
    int warpM = (wid >> 1) * 32, warpN = (wid & 1) * 64;

    // ---- loader mapping: 4x16B cp.async per operand per chunk ----
    int c = tid & 7, rbase = tid >> 3;
    const size_t rsA = (size_t)32 * AROW * 2;   // 32 rows in bytes
    const size_t rsB = (size_t)32 * BROW * 2;
    const char* aRow = (const char*)(A + (size_t)(m0 + rbase) * AROW + c * 8);
    const char* bRow = (const char*)(B + (size_t)(n0 + rbase) * BROW + c * 8);
    uint32_t swo[4];
    #pragma unroll
    for (int i = 0; i < 4; i++) {
        uint32_t bo = (uint32_t)(rbase + 32 * i) * 128 + c * 16;
        swo[i] = bo ^ ((bo >> 3) & 0x70);
    }

    auto koffA = [](int ck) -> size_t {
        int sec = ck / SECLEN;
        int kk  = ck - sec * SECLEN;
        int map = (AMAP >> sec) & 1;
        return ((size_t)map * KLOG + (size_t)kk * 64) * 2;
    };
    auto koffB = [](int ck) -> size_t {
        int sec = ck / SECLEN;
        int kk  = ck - sec * SECLEN;
        int map = (BMAP >> sec) & 1;
        return ((size_t)map * KLOG + (size_t)kk * 64) * 2;
    };

#define LOADCHUNK(STG, CK) do {                                            \
        size_t oa_ = koffA(CK), ob_ = koffB(CK);                           \
        uint32_t ab_ = (STG), bb_ = (STG) + 16384;                         \
        cp16(ab_ + swo[0], aRow + oa_);                                    \
        cp16(ab_ + swo[1], aRow + oa_ + rsA);                              \
        cp16(ab_ + swo[2], aRow + oa_ + 2 * rsA);                          \
        cp16(ab_ + swo[3], aRow + oa_ + 3 * rsA);                          \
        cp16(bb_ + swo[0], bRow + ob_);                                    \
        cp16(bb_ + swo[1], bRow + ob_ + rsB);                              \
        cp16(bb_ + swo[2], bRow + ob_ + 2 * rsB);                          \
        cp16(bb_ + swo[3], bRow + ob_ + 3 * rsB);                          \
        asm volatile("cp.async.commit_group;" ::: "memory");               \
    } while (0)

    // ---- ldmatrix per-lane swizzled offsets ----
    uint32_t aoff[2], boff[4];
    {
        int l = lane;
        #pragma unroll
        for (int mt = 0; mt < 2; mt++) {
            int row = warpM + mt * 16 + (l & 15);
            uint32_t cb = (uint32_t)((l >> 4) << 4);
            aoff[mt] = (uint32_t)row * 128 + (cb ^ (((uint32_t)row & 7) << 4));
        }
        #pragma unroll
        for (int ng = 0; ng < 4; ng++) {
            int row = warpN + ng * 16 + (l & 7) + ((l >> 4) << 3);
            uint32_t cb = (uint32_t)(((l >> 3) & 1) << 4);
            boff[ng] = (uint32_t)row * 128 + (cb ^ (((uint32_t)row & 7) << 4));
        }
    }

    float d[2][8][4];
    #pragma unroll
    for (int mt = 0; mt < 2; mt++)
        #pragma unroll
        for (int nt = 0; nt < 8; nt++)
            #pragma unroll
            for (int q = 0; q < 4; q++) d[mt][nt][q] = 0.f;

    LOADCHUNK(st0, 0);
    LOADCHUNK(st1, 1);

    uint32_t stage[3] = { st0, st1, st2 };
    int cur = 0, nxt = 2;

    for (int ck = 0; ck < NUMK; ck++) {
        if (ck < NUMK - 1) asm volatile("cp.async.wait_group 1;" ::: "memory");
        else               asm volatile("cp.async.wait_group 0;" ::: "memory");
        __syncthreads();

        if (ck + 2 < NUMK) {
            LOADCHUNK(stage[nxt], ck + 2);
            nxt = (nxt == 2) ? 0 : nxt + 1;
        }

        uint32_t ab = stage[cur], bb = stage[cur] + 16384;
        cur = (cur == 2) ? 0 : cur + 1;
        #pragma unroll
        for (int ks = 0; ks < 4; ks++) {
            uint32_t kx = (uint32_t)ks << 5;
            uint32_t a[2][4];
            ldsm4(a[0], ab + (aoff[0] ^ kx));
            ldsm4(a[1], ab + (aoff[1] ^ kx));
            #pragma unroll
            for (int ng = 0; ng < 4; ng++) {
                uint32_t bq[4];
                ldsm4(bq, bb + (boff[ng] ^ kx));
                #pragma unroll
                for (int mt = 0; mt < 2; mt++) {
                    mma16816<HALF>(d[mt][2 * ng],     a[mt], bq[0], bq[1]);
                    mma16816<HALF>(d[mt][2 * ng + 1], a[mt], bq[2], bq[3]);
                }
            }
        }
    }
#undef LOADCHUNK

    // ---- epilogue ----
    int trow = lane >> 2, tcol = (lane & 3) * 2;
    #pragma unroll
    for (int mt = 0; mt < 2; mt++) {
        #pragma unroll
        for (int rr = 0; rr < 2; rr++) {
            size_t grow = (size_t)(m0 + warpM + mt * 16 + trow + rr * 8);
            #pragma unroll
            for (int nt = 0; nt < 8; nt++) {
                int gcol = n0 + warpN + nt * 8 + tcol;
                float v0 = d[mt][nt][rr * 2 + 0];
                float v1 = d[mt][nt][rr * 2 + 1];
                if (EPI == 1 || EPI == 3) {
                    float2 bq = *(const float2*)(bias + gcol);
                    float2 aq = *(const float2*)(addend + ((size_t)z * sC + grow * N) + gcol);
                    v0 = (v0 + bq.x + aq.x) * scale;
                    v1 = (v1 + bq.y + aq.y) * scale;
                } else {
                    v0 *= scale; v1 *= scale;
                }
                if (EPI <= 1) {
                    float* cp = Cf + (size_t)z * sC + grow * N + gcol;
                    *(float2*)cp = make_float2(v0, v1);
                } else if (EPI == 3) {
                    __nv_bfloat16* o = (__nv_bfloat16*)Cs +
                        (size_t)z * sC + grow * (size_t)(2 * N) + gcol;
                    uint32_t hi = f2bf2(v0, v1);
                    uint32_t lo = f2bf2(v0 - bfround(v0), v1 - bfround(v1));
                    *(uint32_t*)(o)     = hi;
                    *(uint32_t*)(o + N) = lo;
                } else {   // EPI == 4 : fp16 single
                    __half* o = (__half*)Cs + (size_t)z * sC + grow * (size_t)N + gcol;
                    *(uint32_t*)o = f2h2(v0, v1);
                }
            }
        }
    }
}

// ===========================================================================
// softmax over S=1024, warp-per-row (8 rows per 256-thr block, no barriers):
// writes f32 in place + single-fp16 copy for K6
// ===========================================================================
__global__ void softmax_f16_kernel(float* __restrict__ attn,
                                   __half* __restrict__ asp)
{
    int lane = threadIdx.x & 31;
    size_t row = (size_t)blockIdx.x * 8 + (threadIdx.x >> 5);
    float* p = attn + row * 1024;

    float4 v[8];
    #pragma unroll
    for (int c2 = 0; c2 < 8; c2++)
        v[c2] = *(const float4*)&p[lane * 4 + c2 * 128];

    float m = -3.4e38f;
    #pragma unroll
    for (int c2 = 0; c2 < 8; c2++)
        m = fmaxf(m, fmaxf(fmaxf(v[c2].x, v[c2].y), fmaxf(v[c2].z, v[c2].w)));
    #pragma unroll
    for (int o = 16; o > 0; o >>= 1) m = fmaxf(m, __shfl_xor_sync(0xffffffffu, m, o));

    float s = 0.f;
    #pragma unroll
    for (int c2 = 0; c2 < 8; c2++) {
        v[c2].x = expf(v[c2].x - m);
        v[c2].y = expf(v[c2].y - m);
        v[c2].z = expf(v[c2].z - m);
        v[c2].w = expf(v[c2].w - m);
        s += (v[c2].x + v[c2].y) + (v[c2].z + v[c2].w);
    }
    #pragma unroll
    for (int o = 16; o > 0; o >>= 1) s += __shfl_xor_sync(0xffffffffu, s, o);
    float inv = 1.f / s;

    __half* ah = asp + row * 1024;
    #pragma unroll
    for (int c2 = 0; c2 < 8; c2++) {
        float o0 = v[c2].x * inv, o1 = v[c2].y * inv;
        float o2 = v[c2].z * inv, o3 = v[c2].w * inv;
        *(float4*)&p[lane * 4 + c2 * 128] = make_float4(o0, o1, o2, o3);
        *(uint2*)&ah[lane * 4 + c2 * 128] = make_uint2(f2h2(o0, o1), f2h2(o2, o3));
    }
}

// ===========================================================================
extern "C" void kernel_launch(void* const* d_in, const int* in_sizes, int n_in,
                              void* d_out, int out_size)
{
    const float* x     = (const float*)d_in[0];
    const float* te    = (const float*)d_in[1];
    const float* enc0  = (const float*)d_in[2];
    const float* enc1  = (const float*)d_in[3];
    const float* enc2  = (const float*)d_in[4];
    const float* in_v  = (const float*)d_in[5];
    const float* in_g  = (const float*)d_in[6];
    const float* in_b  = (const float*)d_in[7];
    const float* out_v = (const float*)d_in[8];
    const float* out_g = (const float*)d_in[9];
    const float* out_b = (const float*)d_in[10];

    float* out  = (float*)d_out;
    float* attn = out + (size_t)64 * 1024 * 512;

    __nv_bfloat16 *xsp, *hsp, *esumT, *winsp;
    __half *attnh, *enc2h, *e2w, *wouth;
    cudaGetSymbolAddress((void**)&xsp,   g_xsplit);
    cudaGetSymbolAddress((void**)&hsp,   g_hsplit);
    cudaGetSymbolAddress((void**)&attnh, g_attn_f16);
    cudaGetSymbolAddress((void**)&esumT, g_esumT);
    cudaGetSymbolAddress((void**)&enc2h, g_enc2h);
    cudaGetSymbolAddress((void**)&e2w,   g_e2w);
    cudaGetSymbolAddress((void**)&winsp, g_winsplit);
    cudaGetSymbolAddress((void**)&wouth, g_wout_f16);

    // instantiations
    auto K1 = mma_gemm<3, 512, 3, 2, 4, 1024, 1024, false>;
    auto K2 = mma_gemm<0, 512, 3, 2, 4, 1024, 1024, false>;
    auto KE = mma_gemm<4, 512, 1, 0, 0, 512, 512, true>;     // E2W = 32*W@enc2^T
    auto K6 = mma_gemm<1, 1024, 1, 0, 0, 1024, 1024, true>;  // out = attn@E2W^T
    cudaFuncSetAttribute(K1, cudaFuncAttributeMaxDynamicSharedMemorySize, SMEM_BYTES);
    cudaFuncSetAttribute(K2, cudaFuncAttributeMaxDynamicSharedMemorySize, SMEM_BYTES);
    cudaFuncSetAttribute(KE, cudaFuncAttributeMaxDynamicSharedMemorySize, SMEM_BYTES);
    cudaFuncSetAttribute(K6, cudaFuncAttributeMaxDynamicSharedMemorySize, SMEM_BYTES);

    // side stream + events for fork/join inside graph capture
    cudaStream_t s1;
    cudaStreamCreateWithFlags(&s1, cudaStreamNonBlocking);
    cudaEvent_t eFork, eWn, eEsum, eE2W, eK1, eB;
    cudaEventCreateWithFlags(&eFork, cudaEventDisableTiming);
    cudaEventCreateWithFlags(&eWn,   cudaEventDisableTiming);
    cudaEventCreateWithFlags(&eEsum, cudaEventDisableTiming);
    cudaEventCreateWithFlags(&eE2W,  cudaEventDisableTiming);
    cudaEventCreateWithFlags(&eK1,   cudaEventDisableTiming);
    cudaEventCreateWithFlags(&eB,    cudaEventDisableTiming);

    // per-half strides/offsets
    const long long sA2 = (long long)1024 * 1024;   // hsp per-batch (elems)
    const long long sB2 = (long long)1024 * 1024;   // esumT per-batch
    const long long sC2 = (long long)1024 * 1024;   // attn per-batch
    const long long sA6 = (long long)1024 * 1024;   // attn_f16 per-batch
    const long long sB6 = (long long)512 * 1024;    // e2w per-batch
    const long long sC6 = (long long)1024 * 512;    // out / x per-batch
    const size_t hx = (size_t)32 * sC6;             // half offset (out, x)

    // ---- fork ----
    cudaEventRecord(eFork, 0);
    cudaStreamWaitEvent(s1, eFork, 0);

    // side stream: K1 weights -> esumT -> E2W pipeline
    wn_split_kernel<<<512, 256, 0, s1>>>(in_v, in_g, winsp, 512);
    cudaEventRecord(eWn, s1);
    transpose_split_kernel<<<dim3(8, 32, 64), 256, 0, s1>>>(
        enc0, enc1, esumT, 512, 1024, (long long)512 * 1024, (long long)1024 * 1024);
    cudaEventRecord(eEsum, s1);
    wn_f16_kernel<<<512, 256, 0, s1>>>(out_v, out_g, wouth, 512);
    f16cvt_kernel<<<16384, 256, 0, s1>>>(enc2, enc2h);
    // E2W[b][c][s] = 32 * sum_e W[c][e]*enc2[b][s][e]   M=512 N=1024 K=512
    KE<<<dim3(8, 4, 64), 256, SMEM_BYTES, s1>>>(
        (const uint16_t*)wouth, (const uint16_t*)enc2h, nullptr, e2w,
        1024, 0LL, (long long)1024 * 512, (long long)512 * 1024,
        nullptr, nullptr, 32.0f);
    cudaEventRecord(eE2W, s1);

    // main stream: input split (overlaps wn_split), then K1
    asplit_kernel<<<16384, 256>>>(x, xsp);
    cudaStreamWaitEvent(0, eWn, 0);
    K1<<<dim3(4, 512, 1), 256, SMEM_BYTES>>>(
        (const uint16_t*)xsp, (const uint16_t*)winsp, nullptr, hsp,
        512, 0LL, 0LL, 0LL, in_b, te, SQRT_HALF_F);

    // join: main needs esumT before K2; side half-B needs K1 done
    cudaStreamWaitEvent(0, eEsum, 0);
    cudaEventRecord(eK1, 0);
    cudaStreamWaitEvent(s1, eK1, 0);

    // main: half A (K2 -> softmax -> K6)
    K2<<<dim3(8, 8, 32), 256, SMEM_BYTES>>>(
        (const uint16_t*)hsp, (const uint16_t*)esumT, attn, nullptr,
        1024, sA2, sB2, sC2, nullptr, nullptr, 1.0f);
    softmax_f16_kernel<<<4096, 256>>>(attn, attnh);
    cudaStreamWaitEvent(0, eE2W, 0);
    K6<<<dim3(4, 8, 32), 256, SMEM_BYTES>>>(
        (const uint16_t*)attnh, (const uint16_t*)e2w, out, nullptr,
        512, sA6, sB6, sC6, out_b, x, SQRT_HALF_F);

    // side: half B (e2w ordered on s1; no extra wait needed)
    K2<<<dim3(8, 8, 32), 256, SMEM_BYTES, s1>>>(
        (const uint16_t*)(hsp + 32 * sA2), (const uint16_t*)(esumT + 32 * sB2),
        attn + 32 * sC2, nullptr, 1024, sA2, sB2, sC2, nullptr, nullptr, 1.0f);
    softmax_f16_kernel<<<4096, 256, 0, s1>>>(attn + 32 * sC2, attnh + 32 * sA6);
    K6<<<dim3(4, 8, 32), 256, SMEM_BYTES, s1>>>(
        (const uint16_t*)(attnh + 32 * sA6), (const uint16_t*)(e2w + 32 * sB6),
        out + hx, nullptr, 512, sA6, sB6, sC6, out_b, x + hx, SQRT_HALF_F);
    cudaEventRecord(eB, s1);

    // final join back onto the capture stream
    cudaStreamWaitEvent(0, eB, 0);
}